// round 10
// baseline (speedup 1.0000x reference)
#include <cuda_runtime.h>
#include <cuda_fp16.h>
#include <cstdint>
#include <cstddef>

// ---------------------------------------------------------------------------
// GATv2 x3 layers.  Dims: 4 -> 128 -> 512 -> 1028, H=32 heads, head-mean.
//   GEMMs: mma.sync.m16n8k16 fp16 (fp32 accum), 128x128 CTA tile, cp.async
//     double buffer, fp32 head-major outputs xl/xr: [h][n][c].
//   Edge phase (v2):
//     lrelu(s) = 0.6 s + 0.4 |s|  ->  e = 0.6(dl[src]+dr[dst]) + 0.4 a.|s|
//     dl/dr precomputed per (node, head); per-edge loop is 2 instr/element.
//     No online max (logits are O(1); exp can't overflow), so no rescale.
// ---------------------------------------------------------------------------

#define MAX_N 10000
#define MAX_E 160000
#define MAX_EL (MAX_E + MAX_N)

// scratch (allocation-free rule: __device__ globals)
__device__ float  g_xl[328960000];          // 10000 * 32 * 1028 (head-major)
__device__ float  g_xr[328960000];
__device__ float  g_acc[328960000];
__device__ float  g_dl[320000];             // N * H
__device__ float  g_dr[320000];
__device__ __half g_wlh[16842752];          // transposed half weights
__device__ __half g_wrh[16842752];
__device__ __half g_a0h[80000];             // x as half, padded K=8
__device__ __half g_h1h[1280000];           // N x 128
__device__ __half g_h2h[5120000];           // N x 512
__device__ int    g_deg[MAX_N];
__device__ int    g_rowptr[MAX_N + 1];
__device__ int    g_cursor[MAX_N];
__device__ int    g_col[MAX_EL];

// ---------------------------------------------------------------------------
// helpers
// ---------------------------------------------------------------------------
__device__ __forceinline__ void cp16(uint32_t dst, const void* src, int bytes) {
    asm volatile("cp.async.cg.shared.global [%0], [%1], 16, %2;"
                 :: "r"(dst), "l"(src), "r"(bytes) : "memory");
}
__device__ __forceinline__ void cp_commit() {
    asm volatile("cp.async.commit_group;" ::: "memory");
}
template <int N>
__device__ __forceinline__ void cp_wait() {
    asm volatile("cp.async.wait_group %0;" :: "n"(N) : "memory");
}
__device__ __forceinline__ uint32_t smem_u32(const void* p) {
    uint32_t a;
    asm("{ .reg .u64 t; cvta.to.shared.u64 t, %1; cvt.u32.u64 %0, t; }"
        : "=r"(a) : "l"(p));
    return a;
}
__device__ __forceinline__ void mma_fp16(float& c0, float& c1, float& c2, float& c3,
                                         uint32_t a0, uint32_t a1, uint32_t a2, uint32_t a3,
                                         uint32_t b0, uint32_t b1) {
    asm volatile(
        "mma.sync.aligned.m16n8k16.row.col.f32.f16.f16.f32 "
        "{%0,%1,%2,%3}, {%4,%5,%6,%7}, {%8,%9}, {%0,%1,%2,%3};"
        : "+f"(c0), "+f"(c1), "+f"(c2), "+f"(c3)
        : "r"(a0), "r"(a1), "r"(a2), "r"(a3), "r"(b0), "r"(b1));
}

// ---------------------------------------------------------------------------
// weight convert + transpose:  Wt[n][k] = (half)W[k][n]
// ---------------------------------------------------------------------------
__global__ void conv_trans_k(const float* __restrict__ W, __half* __restrict__ Wt,
                             int K, int Ncols, int ldwt) {
    __shared__ float t[32][33];
    int n0 = blockIdx.x * 32;
    int k0 = blockIdx.y * 32;
    int tx = threadIdx.x;
    int ty = threadIdx.y;
    for (int i = ty; i < 32; i += 8) {
        int k = k0 + i;
        int n = n0 + tx;
        t[i][tx] = (k < K && n < Ncols) ? W[(size_t)k * Ncols + n] : 0.f;
    }
    __syncthreads();
    for (int i = ty; i < 32; i += 8) {
        int n = n0 + i;
        int k = k0 + tx;
        if (n < Ncols && k < ldwt)
            Wt[(size_t)n * ldwt + k] = __float2half(t[tx][i]);
    }
}

__global__ void conv_x_k(const float* __restrict__ x, __half* __restrict__ out,
                         int N, int K, int lda) {
    int i = blockIdx.x * blockDim.x + threadIdx.x;
    if (i < N * lda) {
        int row = i / lda, col = i - row * lda;
        out[i] = __float2half(col < K ? x[row * K + col] : 0.f);
    }
}

// ---------------------------------------------------------------------------
// fp16 GEMM:  C_out[h][m][c] = (A @ Bt^T)[m, h*C+c] + bias   (head-major fp32)
// ---------------------------------------------------------------------------
#define AS 40
#define TILE_BYTES (128 * AS * 2)           // 10240
#define GEMM_SMEM (4 * TILE_BYTES)          // 40960

__global__ __launch_bounds__(128, 2) void gemm_h_k(
    const __half* __restrict__ A, const __half* __restrict__ Bt,
    const float* __restrict__ bias, float* __restrict__ Cmat,
    int M, int K, int lda, int ldb, int Ncols, int Cdim)
{
    extern __shared__ __align__(16) __half dyn[];
    __half* sA[2] = { dyn,              dyn + TILE_BYTES / 2 };
    __half* sB[2] = { dyn + TILE_BYTES, dyn + 3 * TILE_BYTES / 2 };

    const int tid = threadIdx.x;
    const int wid = tid >> 5;
    const int lane = tid & 31;
    const int gid = lane >> 2;
    const int tig = lane & 3;
    const int m0 = blockIdx.x * 128;
    const int n0 = blockIdx.y * 128;
    const int warpM = (wid >> 1) * 64;
    const int warpN = (wid & 1) * 64;

    const int nChunks = (K + 31) / 32;

    auto stage = [&](int chunk, int b) {
        const int k0 = chunk * 32;
        uint32_t sAu = smem_u32(sA[b]);
        uint32_t sBu = smem_u32(sB[b]);
#pragma unroll
        for (int it = 0; it < 4; it++) {
            int idx = tid + it * 128;
            int row = idx >> 2;
            int seg = (idx & 3) * 8;
            int gk = k0 + seg;
            int rem = (K - gk) * 2;
            int bytes = (m0 + row < M) ? (rem < 0 ? 0 : (rem > 16 ? 16 : rem)) : 0;
            const __half* src = bytes ? &A[(size_t)(m0 + row) * lda + gk] : A;
            cp16(sAu + (row * AS + seg) * 2, src, bytes);
        }
#pragma unroll
        for (int it = 0; it < 4; it++) {
            int idx = tid + it * 128;
            int row = idx >> 2;
            int seg = (idx & 3) * 8;
            int gk = k0 + seg;
            int rem = (K - gk) * 2;
            int bytes = rem < 0 ? 0 : (rem > 16 ? 16 : rem);
            const __half* src = bytes ? &Bt[(size_t)(n0 + row) * ldb + gk] : Bt;
            cp16(sBu + (row * AS + seg) * 2, src, bytes);
        }
        cp_commit();
    };

    float acc[4][8][4];
#pragma unroll
    for (int i = 0; i < 4; i++)
#pragma unroll
        for (int j = 0; j < 8; j++)
#pragma unroll
            for (int q = 0; q < 4; q++) acc[i][j][q] = 0.f;

    stage(0, 0);

    for (int t = 0; t < nChunks; t++) {
        if (t + 1 < nChunks) { stage(t + 1, (t + 1) & 1); cp_wait<1>(); }
        else                 { cp_wait<0>(); }
        __syncthreads();

        const __half* cA = sA[t & 1];
        const __half* cB = sB[t & 1];
#pragma unroll
        for (int kk = 0; kk < 32; kk += 16) {
            uint32_t af[4][4];
#pragma unroll
            for (int i = 0; i < 4; i++) {
                int r = warpM + i * 16 + gid;
                af[i][0] = *(const uint32_t*)&cA[(r)     * AS + kk + 2 * tig];
                af[i][1] = *(const uint32_t*)&cA[(r + 8) * AS + kk + 2 * tig];
                af[i][2] = *(const uint32_t*)&cA[(r)     * AS + kk + 2 * tig + 8];
                af[i][3] = *(const uint32_t*)&cA[(r + 8) * AS + kk + 2 * tig + 8];
            }
            uint32_t bf[8][2];
#pragma unroll
            for (int j = 0; j < 8; j++) {
                int n = warpN + j * 8 + gid;
                bf[j][0] = *(const uint32_t*)&cB[n * AS + kk + 2 * tig];
                bf[j][1] = *(const uint32_t*)&cB[n * AS + kk + 2 * tig + 8];
            }
#pragma unroll
            for (int i = 0; i < 4; i++)
#pragma unroll
                for (int j = 0; j < 8; j++)
                    mma_fp16(acc[i][j][0], acc[i][j][1], acc[i][j][2], acc[i][j][3],
                             af[i][0], af[i][1], af[i][2], af[i][3],
                             bf[j][0], bf[j][1]);
        }
        __syncthreads();
    }

    int hj[8], cj[8];
    float bj0[8], bj1[8];
#pragma unroll
    for (int j = 0; j < 8; j++) {
        int col = n0 + warpN + j * 8 + tig * 2;
        int h = col / Cdim;
        hj[j] = h;
        cj[j] = col - h * Cdim;
        bj0[j] = __ldg(&bias[col]);
        bj1[j] = __ldg(&bias[col + 1]);
    }
#pragma unroll
    for (int i = 0; i < 4; i++) {
        int r0 = m0 + warpM + i * 16 + gid;
#pragma unroll
        for (int j = 0; j < 8; j++) {
            float* base = &Cmat[((size_t)hj[j] * M) * Cdim + cj[j]];
            if (r0 < M) {
                float2 v = make_float2(acc[i][j][0] + bj0[j], acc[i][j][1] + bj1[j]);
                *reinterpret_cast<float2*>(&base[(size_t)r0 * Cdim]) = v;
            }
            if (r0 + 8 < M) {
                float2 v = make_float2(acc[i][j][2] + bj0[j], acc[i][j][3] + bj1[j]);
                *reinterpret_cast<float2*>(&base[(size_t)(r0 + 8) * Cdim]) = v;
            }
        }
    }
}

// ---------------------------------------------------------------------------
// CSR construction
// ---------------------------------------------------------------------------
__global__ void init_deg_k(int* deg, int n) {
    int i = blockIdx.x * blockDim.x + threadIdx.x;
    if (i < n) deg[i] = 1;
}
__global__ void count_deg_k(const int* __restrict__ ei, int* deg, int E) {
    int e = blockIdx.x * blockDim.x + threadIdx.x;
    if (e < E) atomicAdd(&deg[ei[E + e]], 1);
}
__global__ void scan_rowptr_k(const int* __restrict__ deg, int* rowptr, int n) {
    __shared__ int sm[1024];
    __shared__ int carry;
    int tid = threadIdx.x;
    if (tid == 0) { carry = 0; rowptr[0] = 0; }
    __syncthreads();
    for (int base = 0; base < n; base += 1024) {
        int i = base + tid;
        int v = (i < n) ? deg[i] : 0;
        sm[tid] = v;
        __syncthreads();
        for (int off = 1; off < 1024; off <<= 1) {
            int t = (tid >= off) ? sm[tid - off] : 0;
            __syncthreads();
            sm[tid] += t;
            __syncthreads();
        }
        if (i < n) rowptr[i + 1] = carry + sm[tid];
        __syncthreads();
        if (tid == 0) carry += sm[1023];
        __syncthreads();
    }
}
__global__ void copy_cursor_k(const int* __restrict__ rowptr, int* cursor, int n) {
    int i = blockIdx.x * blockDim.x + threadIdx.x;
    if (i < n) cursor[i] = rowptr[i];
}
__global__ void scatter_edges_k(const int* __restrict__ ei, int* cursor,
                                int* colv, int E) {
    int e = blockIdx.x * blockDim.x + threadIdx.x;
    if (e < E) {
        int s = ei[e];
        int d = ei[E + e];
        int pos = atomicAdd(&cursor[d], 1);
        colv[pos] = s;
    }
}
__global__ void scatter_loops_k(int* cursor, int* colv, int n) {
    int i = blockIdx.x * blockDim.x + threadIdx.x;
    if (i < n) {
        int pos = atomicAdd(&cursor[i], 1);
        colv[pos] = i;
    }
}

// ---------------------------------------------------------------------------
// per-(node, head) dot products:  dl[h][n] = att[h].xl[h][n],  dr likewise
// ---------------------------------------------------------------------------
template <int NV, bool EXACT>
__global__ __launch_bounds__(128) void dot4_k(
    const float4* __restrict__ xl, const float4* __restrict__ xr,
    const float4* __restrict__ att,
    float* __restrict__ dl, float* __restrict__ dr, int C4, int Nn)
{
    int n = blockIdx.x;
    int h = blockIdx.y;
    int tid = threadIdx.x;
    __shared__ float wsl[4], wsr[4];

    size_t base = ((size_t)h * Nn + n) * C4;
    float pl = 0.f, pr = 0.f;
#pragma unroll
    for (int j = 0; j < NV; j++) {
        int idx = tid + j * 128;
        if (EXACT || idx < C4) {
            float4 a4 = __ldg(&att[(size_t)h * C4 + idx]);
            float4 l4 = __ldg(&xl[base + idx]);
            float4 r4 = __ldg(&xr[base + idx]);
            pl += a4.x * l4.x + a4.y * l4.y + a4.z * l4.z + a4.w * l4.w;
            pr += a4.x * r4.x + a4.y * r4.y + a4.z * r4.z + a4.w * r4.w;
        }
    }
#pragma unroll
    for (int o = 16; o > 0; o >>= 1) {
        pl += __shfl_xor_sync(0xffffffffu, pl, o);
        pr += __shfl_xor_sync(0xffffffffu, pr, o);
    }
    if ((tid & 31) == 0) { wsl[tid >> 5] = pl; wsr[tid >> 5] = pr; }
    __syncthreads();
    if (tid == 0) {
        dl[(size_t)h * Nn + n] = wsl[0] + wsl[1] + wsl[2] + wsl[3];
        dr[(size_t)h * Nn + n] = wsr[0] + wsr[1] + wsr[2] + wsr[3];
    }
}

// ---------------------------------------------------------------------------
// Edge attention v2, scalar path (C == 128).  Block = (dst, head), 128 thr.
// e = 0.6(dl[src]+dr[dst]) + 0.4 * sum a|s|;  no max tracking, no rescale.
// ---------------------------------------------------------------------------
__global__ __launch_bounds__(128) void gat_edge_k(
    const float* __restrict__ xl, const float* __restrict__ xr,
    const float* __restrict__ att,
    const float* __restrict__ dl, const float* __restrict__ dr,
    const int* __restrict__ rowptr, const int* __restrict__ colv,
    float* __restrict__ accm, int C, int Nn)
{
    int dst = blockIdx.x;
    int h = blockIdx.y;
    int tid = threadIdx.x;
    __shared__ float ws[2][4];

    const float* xlh = xl + (size_t)h * Nn * C;
    float a = att[h * C + tid];
    float xd = xr[((size_t)h * Nn + dst) * C + tid];
    float dr_d = dr[(size_t)h * Nn + dst];
    float acc = 0.f, l = 0.f;

    int e0 = rowptr[dst], e1 = rowptr[dst + 1];
    for (int e = e0; e < e1; e++) {
        int s = __ldg(&colv[e]);
        float dls = __ldg(&dl[(size_t)h * Nn + s]);
        float xv = __ldg(&xlh[(size_t)s * C + tid]);
        float p = a * fabsf(xv + xd);
#pragma unroll
        for (int o = 16; o > 0; o >>= 1) p += __shfl_xor_sync(0xffffffffu, p, o);
        int slot = e & 1;
        if ((tid & 31) == 0) ws[slot][tid >> 5] = p;
        __syncthreads();
        float pv = ws[slot][0] + ws[slot][1] + ws[slot][2] + ws[slot][3];
        float w = __expf(0.6f * (dls + dr_d) + 0.4f * pv);
        acc += w * xv;
        l += w;
    }
    accm[((size_t)h * Nn + dst) * C + tid] = acc / l;
}

// ---------------------------------------------------------------------------
// Edge attention v2, float4 path.  Block = (dst, head), 128 thr, 2 edges/bar.
// ---------------------------------------------------------------------------
template <int NV, bool EXACT>
__global__ __launch_bounds__(128) void gat_edge4_k(
    const float4* __restrict__ xl, const float4* __restrict__ xr,
    const float4* __restrict__ att,
    const float* __restrict__ dl, const float* __restrict__ dr,
    const int* __restrict__ rowptr, const int* __restrict__ colv,
    float4* __restrict__ accm, int C4, int Nn)
{
    int dst = blockIdx.x;
    int h = blockIdx.y;
    int tid = threadIdx.x;
    __shared__ float ws[2][2][4];

    const float4* xlh = xl + (size_t)h * Nn * C4;
    const float4* xrh = xr + (size_t)h * Nn * C4;
    const float4 z4 = make_float4(0.f, 0.f, 0.f, 0.f);
    const float* dlh = dl + (size_t)h * Nn;

    float4 a[NV], xd[NV], acc[NV];
#pragma unroll
    for (int j = 0; j < NV; j++) {
        int idx = tid + j * 128;
        bool ok = EXACT || (idx < C4);
        a[j]   = ok ? __ldg(&att[(size_t)h * C4 + idx]) : z4;
        xd[j]  = ok ? __ldg(&xrh[(size_t)dst * C4 + idx]) : z4;
        acc[j] = z4;
    }
    float dr_d = dr[(size_t)h * Nn + dst];
    float l = 0.f;

    int e0 = rowptr[dst], e1 = rowptr[dst + 1];
    int deg = e1 - e0;
    int npair = deg >> 1;

    for (int it = 0; it < npair; it++) {
        int e = e0 + it * 2;
        int s0 = __ldg(&colv[e]);
        int s1 = __ldg(&colv[e + 1]);
        float dl0 = __ldg(&dlh[s0]);
        float dl1 = __ldg(&dlh[s1]);
        const float4* v0 = xlh + (size_t)s0 * C4;
        const float4* v1 = xlh + (size_t)s1 * C4;
        float4 xs0[NV], xs1[NV];
        float p0 = 0.f, p1 = 0.f;
#pragma unroll
        for (int j = 0; j < NV; j++) {
            int idx = tid + j * 128;
            bool ok = EXACT || (idx < C4);
            float4 x0 = ok ? __ldg(&v0[idx]) : z4;
            float4 x1 = ok ? __ldg(&v1[idx]) : z4;
            xs0[j] = x0; xs1[j] = x1;
            p0 = fmaf(a[j].x, fabsf(x0.x + xd[j].x), p0);
            p0 = fmaf(a[j].y, fabsf(x0.y + xd[j].y), p0);
            p0 = fmaf(a[j].z, fabsf(x0.z + xd[j].z), p0);
            p0 = fmaf(a[j].w, fabsf(x0.w + xd[j].w), p0);
            p1 = fmaf(a[j].x, fabsf(x1.x + xd[j].x), p1);
            p1 = fmaf(a[j].y, fabsf(x1.y + xd[j].y), p1);
            p1 = fmaf(a[j].z, fabsf(x1.z + xd[j].z), p1);
            p1 = fmaf(a[j].w, fabsf(x1.w + xd[j].w), p1);
        }
#pragma unroll
        for (int o = 16; o > 0; o >>= 1) {
            p0 += __shfl_xor_sync(0xffffffffu, p0, o);
            p1 += __shfl_xor_sync(0xffffffffu, p1, o);
        }
        int sl = it & 1;
        if ((tid & 31) == 0) {
            ws[sl][0][tid >> 5] = p0;
            ws[sl][1][tid >> 5] = p1;
        }
        __syncthreads();
        float pv0 = ws[sl][0][0] + ws[sl][0][1] + ws[sl][0][2] + ws[sl][0][3];
        float pv1 = ws[sl][1][0] + ws[sl][1][1] + ws[sl][1][2] + ws[sl][1][3];

        float w0 = __expf(0.6f * (dl0 + dr_d) + 0.4f * pv0);
        float w1 = __expf(0.6f * (dl1 + dr_d) + 0.4f * pv1);
#pragma unroll
        for (int j = 0; j < NV; j++) {
            acc[j].x += w0 * xs0[j].x + w1 * xs1[j].x;
            acc[j].y += w0 * xs0[j].y + w1 * xs1[j].y;
            acc[j].z += w0 * xs0[j].z + w1 * xs1[j].z;
            acc[j].w += w0 * xs0[j].w + w1 * xs1[j].w;
        }
        l += w0 + w1;
    }

    if (deg & 1) {
        int e = e1 - 1;
        int s0 = __ldg(&colv[e]);
        float dl0 = __ldg(&dlh[s0]);
        const float4* v0 = xlh + (size_t)s0 * C4;
        float4 xs0[NV];
        float p0 = 0.f;
#pragma unroll
        for (int j = 0; j < NV; j++) {
            int idx = tid + j * 128;
            bool ok = EXACT || (idx < C4);
            float4 x0 = ok ? __ldg(&v0[idx]) : z4;
            xs0[j] = x0;
            p0 = fmaf(a[j].x, fabsf(x0.x + xd[j].x), p0);
            p0 = fmaf(a[j].y, fabsf(x0.y + xd[j].y), p0);
            p0 = fmaf(a[j].z, fabsf(x0.z + xd[j].z), p0);
            p0 = fmaf(a[j].w, fabsf(x0.w + xd[j].w), p0);
        }
#pragma unroll
        for (int o = 16; o > 0; o >>= 1) p0 += __shfl_xor_sync(0xffffffffu, p0, o);
        int sl = npair & 1;
        if ((tid & 31) == 0) ws[sl][0][tid >> 5] = p0;
        __syncthreads();
        float pv0 = ws[sl][0][0] + ws[sl][0][1] + ws[sl][0][2] + ws[sl][0][3];
        float w0 = __expf(0.6f * (dl0 + dr_d) + 0.4f * pv0);
#pragma unroll
        for (int j = 0; j < NV; j++) {
            acc[j].x += w0 * xs0[j].x;
            acc[j].y += w0 * xs0[j].y;
            acc[j].z += w0 * xs0[j].z;
            acc[j].w += w0 * xs0[j].w;
        }
        l += w0;
    }

    float inv = 1.f / l;
    float4* dp = accm + ((size_t)h * Nn + dst) * C4;
#pragma unroll
    for (int j = 0; j < NV; j++) {
        int idx = tid + j * 128;
        if (EXACT || idx < C4) {
            float4 v = acc[j];
            v.x *= inv; v.y *= inv; v.z *= inv; v.w *= inv;
            dp[idx] = v;
        }
    }
}

// ---------------------------------------------------------------------------
// Head mean + bias + optional leaky; writes float (final) or half (next layer)
// ---------------------------------------------------------------------------
template <typename T>
__global__ void mean_bias_act_k(const float* __restrict__ accm,
                                const float* __restrict__ bias,
                                T* __restrict__ out,
                                int total, int C, size_t sliceN, int H,
                                float invH, float slope, int do_act) {
    int i = blockIdx.x * blockDim.x + threadIdx.x;
    if (i >= total) return;
    float s = 0.f;
    for (int h = 0; h < H; h++) s += accm[(size_t)h * sliceN + i];
    float v = s * invH + bias[i % C];
    if (do_act) v = v > 0.f ? v : slope * v;
    out[i] = (T)v;
}

// ---------------------------------------------------------------------------
// host orchestration
// ---------------------------------------------------------------------------
static void run_gemm(const __half* A, const __half* Bt, const float* bias,
                     float* C, int M, int K, int lda, int ldb, int Ncols, int Cdim) {
    dim3 grid((M + 127) / 128, Ncols / 128);
    gemm_h_k<<<grid, 128, GEMM_SMEM>>>(A, Bt, bias, C, M, K, lda, ldb, Ncols, Cdim);
}

template <typename TOUT>
static void run_layer(const __half* hin, int fi, int lda, int fo,
                      const float* Wl, const float* bl,
                      const float* Wr, const float* br,
                      const float* att, const float* bias,
                      float* xl, float* xr, float* accm,
                      float* dl, float* dr,
                      __half* wlh, __half* wrh,
                      const int* rowptr, const int* colv,
                      TOUT* hout, int N, int H, bool act) {
    int Ncols = H * fo;
    int ldwt = (fi + 7) & ~7;
    {
        dim3 tb(32, 8);
        dim3 tg((Ncols + 31) / 32, (ldwt + 31) / 32);
        conv_trans_k<<<tg, tb>>>(Wl, wlh, fi, Ncols, ldwt);
        conv_trans_k<<<tg, tb>>>(Wr, wrh, fi, Ncols, ldwt);
    }
    run_gemm(hin, wlh, bl, xl, N, fi, lda, ldwt, Ncols, fo);
    run_gemm(hin, wrh, br, xr, N, fi, lda, ldwt, Ncols, fo);

    dim3 eg(N, H);
    int C4 = fo / 4;
    if (fo == 128) {
        dot4_k<1, false><<<eg, 128>>>((const float4*)xl, (const float4*)xr,
                                      (const float4*)att, dl, dr, C4, N);
        gat_edge_k<<<eg, 128>>>(xl, xr, att, dl, dr, rowptr, colv, accm, fo, N);
    } else if (fo == 512) {
        dot4_k<1, true><<<eg, 128>>>((const float4*)xl, (const float4*)xr,
                                     (const float4*)att, dl, dr, C4, N);
        gat_edge4_k<1, true><<<eg, 128>>>(
            (const float4*)xl, (const float4*)xr, (const float4*)att,
            dl, dr, rowptr, colv, (float4*)accm, C4, N);
    } else {  // 1028 -> C4 = 257
        dot4_k<3, false><<<eg, 128>>>((const float4*)xl, (const float4*)xr,
                                      (const float4*)att, dl, dr, C4, N);
        gat_edge4_k<3, false><<<eg, 128>>>(
            (const float4*)xl, (const float4*)xr, (const float4*)att,
            dl, dr, rowptr, colv, (float4*)accm, C4, N);
    }

    int total = N * fo;
    mean_bias_act_k<TOUT><<<(total + 255) / 256, 256>>>(
        accm, bias, hout, total, fo, (size_t)N * fo, H,
        1.f / (float)H, 0.01f, act ? 1 : 0);
}

extern "C" void kernel_launch(void* const* d_in, const int* in_sizes, int n_in,
                              void* d_out, int out_size) {
    const float* x  = (const float*)d_in[0];
    const int*   ei = (const int*)d_in[1];

    const float* W1l = (const float*)d_in[2];
    const float* b1l = (const float*)d_in[3];
    const float* W1r = (const float*)d_in[4];
    const float* b1r = (const float*)d_in[5];
    const float* at1 = (const float*)d_in[6];
    const float* bi1 = (const float*)d_in[7];
    const float* W2l = (const float*)d_in[8];
    const float* b2l = (const float*)d_in[9];
    const float* W2r = (const float*)d_in[10];
    const float* b2r = (const float*)d_in[11];
    const float* at2 = (const float*)d_in[12];
    const float* bi2 = (const float*)d_in[13];
    const float* W3l = (const float*)d_in[14];
    const float* b3l = (const float*)d_in[15];
    const float* W3r = (const float*)d_in[16];
    const float* b3r = (const float*)d_in[17];
    const float* at3 = (const float*)d_in[18];
    const float* bi3 = (const float*)d_in[19];

    int N = in_sizes[0] / 4;
    int E = in_sizes[1] / 2;
    int f1 = in_sizes[7];
    int f2 = in_sizes[13];
    int f3 = in_sizes[19];
    int H  = in_sizes[3] / f1;

    cudaFuncSetAttribute(gemm_h_k, cudaFuncAttributeMaxDynamicSharedMemorySize,
                         GEMM_SMEM);

    float *xl, *xr, *accm, *dl, *dr;
    __half *wlh, *wrh, *a0h, *h1h, *h2h;
    int *deg, *rowptr, *cursor, *colv;
    cudaGetSymbolAddress((void**)&xl, g_xl);
    cudaGetSymbolAddress((void**)&xr, g_xr);
    cudaGetSymbolAddress((void**)&accm, g_acc);
    cudaGetSymbolAddress((void**)&dl, g_dl);
    cudaGetSymbolAddress((void**)&dr, g_dr);
    cudaGetSymbolAddress((void**)&wlh, g_wlh);
    cudaGetSymbolAddress((void**)&wrh, g_wrh);
    cudaGetSymbolAddress((void**)&a0h, g_a0h);
    cudaGetSymbolAddress((void**)&h1h, g_h1h);
    cudaGetSymbolAddress((void**)&h2h, g_h2h);
    cudaGetSymbolAddress((void**)&deg, g_deg);
    cudaGetSymbolAddress((void**)&rowptr, g_rowptr);
    cudaGetSymbolAddress((void**)&cursor, g_cursor);
    cudaGetSymbolAddress((void**)&colv, g_col);

    // --- CSR build (by destination) ---
    init_deg_k<<<(N + 255) / 256, 256>>>(deg, N);
    count_deg_k<<<(E + 255) / 256, 256>>>(ei, deg, E);
    scan_rowptr_k<<<1, 1024>>>(deg, rowptr, N);
    copy_cursor_k<<<(N + 255) / 256, 256>>>(rowptr, cursor, N);
    scatter_edges_k<<<(E + 255) / 256, 256>>>(ei, cursor, colv, E);
    scatter_loops_k<<<(N + 255) / 256, 256>>>(cursor, colv, N);

    // --- x -> half (padded to 8 columns) ---
    conv_x_k<<<(N * 8 + 255) / 256, 256>>>(x, a0h, N, 4, 8);

    // --- 3 GATv2 layers ---
    run_layer<__half>(a0h, 4, 8, f1, W1l, b1l, W1r, b1r, at1, bi1,
                      xl, xr, accm, dl, dr, wlh, wrh, rowptr, colv, h1h, N, H, true);
    run_layer<__half>(h1h, f1, f1, f2, W2l, b2l, W2r, b2r, at2, bi2,
                      xl, xr, accm, dl, dr, wlh, wrh, rowptr, colv, h2h, N, H, true);
    run_layer<float>(h2h, f2, f2, f3, W3l, b3l, W3r, b3r, at3, bi3,
                     xl, xr, accm, dl, dr, wlh, wrh, rowptr, colv, (float*)d_out, N, H, false);
}

// round 11
// speedup vs baseline: 1.0095x; 1.0095x over previous
#include <cuda_runtime.h>
#include <cuda_fp16.h>
#include <cstdint>
#include <cstddef>

// ---------------------------------------------------------------------------
// GATv2 x3 layers.  Dims: 4 -> 128 -> 512 -> 1028, H=32 heads, head-mean.
//   GEMMs: mma.sync.m16n8k16 fp16 (fp32 accum), 128x128 CTA tile, cp.async
//     double buffer, fp32 head-major outputs xl/xr: [h][n][c].
//   Edge phase (two-phase, barrier-free):
//     A) warp per 8 (edge,head): w[h][e] = exp(sum a.lrelu(xl[src]+xr[dst]))
//        -- warp shuffles only, no block sync, massive parallelism.
//     B) block per (dst,head): acc = sum w[e].xl[src], l = sum w[e]
//        -- pure LDG+FFMA stream, zero synchronization.
// ---------------------------------------------------------------------------

#define MAX_N 10000
#define MAX_E 160000
#define MAX_EL (MAX_E + MAX_N)

// scratch (allocation-free rule: __device__ globals)
__device__ float  g_xl[328960000];          // 10000 * 32 * 1028 (head-major)
__device__ float  g_xr[328960000];
__device__ float  g_acc[328960000];
__device__ float  g_w[5440000];             // H * (E+N) edge weights
__device__ __half g_wlh[16842752];          // transposed half weights
__device__ __half g_wrh[16842752];
__device__ __half g_a0h[80000];             // x as half, padded K=8
__device__ __half g_h1h[1280000];           // N x 128
__device__ __half g_h2h[5120000];           // N x 512
__device__ int    g_deg[MAX_N];
__device__ int    g_rowptr[MAX_N + 1];
__device__ int    g_cursor[MAX_N];
__device__ int    g_col[MAX_EL];
__device__ int    g_dst[MAX_EL];

// ---------------------------------------------------------------------------
// helpers
// ---------------------------------------------------------------------------
__device__ __forceinline__ void cp16(uint32_t dst, const void* src, int bytes) {
    asm volatile("cp.async.cg.shared.global [%0], [%1], 16, %2;"
                 :: "r"(dst), "l"(src), "r"(bytes) : "memory");
}
__device__ __forceinline__ void cp_commit() {
    asm volatile("cp.async.commit_group;" ::: "memory");
}
template <int N>
__device__ __forceinline__ void cp_wait() {
    asm volatile("cp.async.wait_group %0;" :: "n"(N) : "memory");
}
__device__ __forceinline__ uint32_t smem_u32(const void* p) {
    uint32_t a;
    asm("{ .reg .u64 t; cvta.to.shared.u64 t, %1; cvt.u32.u64 %0, t; }"
        : "=r"(a) : "l"(p));
    return a;
}
__device__ __forceinline__ void mma_fp16(float& c0, float& c1, float& c2, float& c3,
                                         uint32_t a0, uint32_t a1, uint32_t a2, uint32_t a3,
                                         uint32_t b0, uint32_t b1) {
    asm volatile(
        "mma.sync.aligned.m16n8k16.row.col.f32.f16.f16.f32 "
        "{%0,%1,%2,%3}, {%4,%5,%6,%7}, {%8,%9}, {%0,%1,%2,%3};"
        : "+f"(c0), "+f"(c1), "+f"(c2), "+f"(c3)
        : "r"(a0), "r"(a1), "r"(a2), "r"(a3), "r"(b0), "r"(b1));
}
__device__ __forceinline__ float lrelu02(float v) {
    return v > 0.f ? v : 0.2f * v;
}

// ---------------------------------------------------------------------------
// weight convert + transpose:  Wt[n][k] = (half)W[k][n]
// ---------------------------------------------------------------------------
__global__ void conv_trans_k(const float* __restrict__ W, __half* __restrict__ Wt,
                             int K, int Ncols, int ldwt) {
    __shared__ float t[32][33];
    int n0 = blockIdx.x * 32;
    int k0 = blockIdx.y * 32;
    int tx = threadIdx.x;
    int ty = threadIdx.y;
    for (int i = ty; i < 32; i += 8) {
        int k = k0 + i;
        int n = n0 + tx;
        t[i][tx] = (k < K && n < Ncols) ? W[(size_t)k * Ncols + n] : 0.f;
    }
    __syncthreads();
    for (int i = ty; i < 32; i += 8) {
        int n = n0 + i;
        int k = k0 + tx;
        if (n < Ncols && k < ldwt)
            Wt[(size_t)n * ldwt + k] = __float2half(t[tx][i]);
    }
}

__global__ void conv_x_k(const float* __restrict__ x, __half* __restrict__ out,
                         int N, int K, int lda) {
    int i = blockIdx.x * blockDim.x + threadIdx.x;
    if (i < N * lda) {
        int row = i / lda, col = i - row * lda;
        out[i] = __float2half(col < K ? x[row * K + col] : 0.f);
    }
}

// ---------------------------------------------------------------------------
// fp16 GEMM:  C_out[h][m][c] = (A @ Bt^T)[m, h*C+c] + bias   (head-major fp32)
// ---------------------------------------------------------------------------
#define AS 40
#define TILE_BYTES (128 * AS * 2)           // 10240
#define GEMM_SMEM (4 * TILE_BYTES)          // 40960

__global__ __launch_bounds__(128, 2) void gemm_h_k(
    const __half* __restrict__ A, const __half* __restrict__ Bt,
    const float* __restrict__ bias, float* __restrict__ Cmat,
    int M, int K, int lda, int ldb, int Ncols, int Cdim)
{
    extern __shared__ __align__(16) __half dyn[];
    __half* sA[2] = { dyn,              dyn + TILE_BYTES / 2 };
    __half* sB[2] = { dyn + TILE_BYTES, dyn + 3 * TILE_BYTES / 2 };

    const int tid = threadIdx.x;
    const int wid = tid >> 5;
    const int lane = tid & 31;
    const int gid = lane >> 2;
    const int tig = lane & 3;
    const int m0 = blockIdx.x * 128;
    const int n0 = blockIdx.y * 128;
    const int warpM = (wid >> 1) * 64;
    const int warpN = (wid & 1) * 64;

    const int nChunks = (K + 31) / 32;

    auto stage = [&](int chunk, int b) {
        const int k0 = chunk * 32;
        uint32_t sAu = smem_u32(sA[b]);
        uint32_t sBu = smem_u32(sB[b]);
#pragma unroll
        for (int it = 0; it < 4; it++) {
            int idx = tid + it * 128;
            int row = idx >> 2;
            int seg = (idx & 3) * 8;
            int gk = k0 + seg;
            int rem = (K - gk) * 2;
            int bytes = (m0 + row < M) ? (rem < 0 ? 0 : (rem > 16 ? 16 : rem)) : 0;
            const __half* src = bytes ? &A[(size_t)(m0 + row) * lda + gk] : A;
            cp16(sAu + (row * AS + seg) * 2, src, bytes);
        }
#pragma unroll
        for (int it = 0; it < 4; it++) {
            int idx = tid + it * 128;
            int row = idx >> 2;
            int seg = (idx & 3) * 8;
            int gk = k0 + seg;
            int rem = (K - gk) * 2;
            int bytes = rem < 0 ? 0 : (rem > 16 ? 16 : rem);
            const __half* src = bytes ? &Bt[(size_t)(n0 + row) * ldb + gk] : Bt;
            cp16(sBu + (row * AS + seg) * 2, src, bytes);
        }
        cp_commit();
    };

    float acc[4][8][4];
#pragma unroll
    for (int i = 0; i < 4; i++)
#pragma unroll
        for (int j = 0; j < 8; j++)
#pragma unroll
            for (int q = 0; q < 4; q++) acc[i][j][q] = 0.f;

    stage(0, 0);

    for (int t = 0; t < nChunks; t++) {
        if (t + 1 < nChunks) { stage(t + 1, (t + 1) & 1); cp_wait<1>(); }
        else                 { cp_wait<0>(); }
        __syncthreads();

        const __half* cA = sA[t & 1];
        const __half* cB = sB[t & 1];
#pragma unroll
        for (int kk = 0; kk < 32; kk += 16) {
            uint32_t af[4][4];
#pragma unroll
            for (int i = 0; i < 4; i++) {
                int r = warpM + i * 16 + gid;
                af[i][0] = *(const uint32_t*)&cA[(r)     * AS + kk + 2 * tig];
                af[i][1] = *(const uint32_t*)&cA[(r + 8) * AS + kk + 2 * tig];
                af[i][2] = *(const uint32_t*)&cA[(r)     * AS + kk + 2 * tig + 8];
                af[i][3] = *(const uint32_t*)&cA[(r + 8) * AS + kk + 2 * tig + 8];
            }
            uint32_t bf[8][2];
#pragma unroll
            for (int j = 0; j < 8; j++) {
                int n = warpN + j * 8 + gid;
                bf[j][0] = *(const uint32_t*)&cB[n * AS + kk + 2 * tig];
                bf[j][1] = *(const uint32_t*)&cB[n * AS + kk + 2 * tig + 8];
            }
#pragma unroll
            for (int i = 0; i < 4; i++)
#pragma unroll
                for (int j = 0; j < 8; j++)
                    mma_fp16(acc[i][j][0], acc[i][j][1], acc[i][j][2], acc[i][j][3],
                             af[i][0], af[i][1], af[i][2], af[i][3],
                             bf[j][0], bf[j][1]);
        }
        __syncthreads();
    }

    int hj[8], cj[8];
    float bj0[8], bj1[8];
#pragma unroll
    for (int j = 0; j < 8; j++) {
        int col = n0 + warpN + j * 8 + tig * 2;
        int h = col / Cdim;
        hj[j] = h;
        cj[j] = col - h * Cdim;
        bj0[j] = __ldg(&bias[col]);
        bj1[j] = __ldg(&bias[col + 1]);
    }
#pragma unroll
    for (int i = 0; i < 4; i++) {
        int r0 = m0 + warpM + i * 16 + gid;
#pragma unroll
        for (int j = 0; j < 8; j++) {
            float* base = &Cmat[((size_t)hj[j] * M) * Cdim + cj[j]];
            if (r0 < M) {
                float2 v = make_float2(acc[i][j][0] + bj0[j], acc[i][j][1] + bj1[j]);
                *reinterpret_cast<float2*>(&base[(size_t)r0 * Cdim]) = v;
            }
            if (r0 + 8 < M) {
                float2 v = make_float2(acc[i][j][2] + bj0[j], acc[i][j][3] + bj1[j]);
                *reinterpret_cast<float2*>(&base[(size_t)(r0 + 8) * Cdim]) = v;
            }
        }
    }
}

// ---------------------------------------------------------------------------
// CSR construction (also records per-edge dst for the logit phase)
// ---------------------------------------------------------------------------
__global__ void init_deg_k(int* deg, int n) {
    int i = blockIdx.x * blockDim.x + threadIdx.x;
    if (i < n) deg[i] = 1;
}
__global__ void count_deg_k(const int* __restrict__ ei, int* deg, int E) {
    int e = blockIdx.x * blockDim.x + threadIdx.x;
    if (e < E) atomicAdd(&deg[ei[E + e]], 1);
}
__global__ void scan_rowptr_k(const int* __restrict__ deg, int* rowptr, int n) {
    __shared__ int sm[1024];
    __shared__ int carry;
    int tid = threadIdx.x;
    if (tid == 0) { carry = 0; rowptr[0] = 0; }
    __syncthreads();
    for (int base = 0; base < n; base += 1024) {
        int i = base + tid;
        int v = (i < n) ? deg[i] : 0;
        sm[tid] = v;
        __syncthreads();
        for (int off = 1; off < 1024; off <<= 1) {
            int t = (tid >= off) ? sm[tid - off] : 0;
            __syncthreads();
            sm[tid] += t;
            __syncthreads();
        }
        if (i < n) rowptr[i + 1] = carry + sm[tid];
        __syncthreads();
        if (tid == 0) carry += sm[1023];
        __syncthreads();
    }
}
__global__ void copy_cursor_k(const int* __restrict__ rowptr, int* cursor, int n) {
    int i = blockIdx.x * blockDim.x + threadIdx.x;
    if (i < n) cursor[i] = rowptr[i];
}
__global__ void scatter_edges_k(const int* __restrict__ ei, int* cursor,
                                int* colv, int* dstv, int E) {
    int e = blockIdx.x * blockDim.x + threadIdx.x;
    if (e < E) {
        int s = ei[e];
        int d = ei[E + e];
        int pos = atomicAdd(&cursor[d], 1);
        colv[pos] = s;
        dstv[pos] = d;
    }
}
__global__ void scatter_loops_k(int* cursor, int* colv, int* dstv, int n) {
    int i = blockIdx.x * blockDim.x + threadIdx.x;
    if (i < n) {
        int pos = atomicAdd(&cursor[i], 1);
        colv[pos] = i;
        dstv[pos] = i;
    }
}

// ---------------------------------------------------------------------------
// Phase A: edge logits.  Warp per 8 (edge, head); shuffle reduce only.
// w[h][e] = exp( sum_c att[h][c] * lrelu02(xl[h][src][c] + xr[h][dst][c]) )
// ---------------------------------------------------------------------------
template <int NV, bool EXACT>
__global__ __launch_bounds__(256) void gat_logit_k(
    const float4* __restrict__ xl, const float4* __restrict__ xr,
    const float4* __restrict__ att, const int* __restrict__ srcv,
    const int* __restrict__ dstv, float* __restrict__ w,
    int C4, int Nn, int Etot)
{
    int h = blockIdx.y;
    int warp = threadIdx.x >> 5;
    int lane = threadIdx.x & 31;
    int ebase = (blockIdx.x * 8 + warp) * 8;
    if (ebase >= Etot) return;

    const float4 z4 = make_float4(0.f, 0.f, 0.f, 0.f);
    float4 a[NV];
#pragma unroll
    for (int j = 0; j < NV; j++) {
        int idx = lane + 32 * j;
        a[j] = (EXACT || idx < C4) ? __ldg(&att[(size_t)h * C4 + idx]) : z4;
    }
    const float4* xlh = xl + (size_t)h * Nn * C4;
    const float4* xrh = xr + (size_t)h * Nn * C4;
    float* wh = w + (size_t)h * Etot;

    int eend = ebase + 8 < Etot ? ebase + 8 : Etot;
    for (int e = ebase; e < eend; e++) {
        int s = __ldg(&srcv[e]);
        int d = __ldg(&dstv[e]);
        const float4* ps = xlh + (size_t)s * C4;
        const float4* pd = xrh + (size_t)d * C4;
        float p = 0.f;
#pragma unroll
        for (int j = 0; j < NV; j++) {
            int idx = lane + 32 * j;
            if (EXACT || idx < C4) {
                float4 xv = __ldg(&ps[idx]);
                float4 rv = __ldg(&pd[idx]);
                p = fmaf(a[j].x, lrelu02(xv.x + rv.x), p);
                p = fmaf(a[j].y, lrelu02(xv.y + rv.y), p);
                p = fmaf(a[j].z, lrelu02(xv.z + rv.z), p);
                p = fmaf(a[j].w, lrelu02(xv.w + rv.w), p);
            }
        }
#pragma unroll
        for (int o = 16; o > 0; o >>= 1) p += __shfl_xor_sync(0xffffffffu, p, o);
        if (lane == 0) wh[e] = __expf(p);
    }
}

// ---------------------------------------------------------------------------
// Phase B: weighted sum, barrier-free.  Block per (dst, head).
// Scalar path (C == 128): thread = channel.
// ---------------------------------------------------------------------------
__global__ __launch_bounds__(128) void gat_sum_k(
    const float* __restrict__ xl, const float* __restrict__ w,
    const int* __restrict__ rowptr, const int* __restrict__ colv,
    float* __restrict__ accm, int C, int Nn, int Etot)
{
    int dst = blockIdx.x;
    int h = blockIdx.y;
    int tid = threadIdx.x;
    const float* xlh = xl + (size_t)h * Nn * C;
    const float* wh = w + (size_t)h * Etot;

    float acc = 0.f, l = 0.f;
    int e0 = rowptr[dst], e1 = rowptr[dst + 1];
    int e = e0;
    for (; e + 1 < e1; e += 2) {
        int s0 = __ldg(&colv[e]);
        int s1 = __ldg(&colv[e + 1]);
        float w0 = __ldg(&wh[e]);
        float w1 = __ldg(&wh[e + 1]);
        float x0 = __ldg(&xlh[(size_t)s0 * C + tid]);
        float x1 = __ldg(&xlh[(size_t)s1 * C + tid]);
        acc += w0 * x0 + w1 * x1;
        l += w0 + w1;
    }
    if (e < e1) {
        int s0 = __ldg(&colv[e]);
        float w0 = __ldg(&wh[e]);
        acc += w0 * __ldg(&xlh[(size_t)s0 * C + tid]);
        l += w0;
    }
    accm[((size_t)h * Nn + dst) * C + tid] = acc / l;
}

// float4 path.  NV = ceil(C4 / 128).
template <int NV, bool EXACT>
__global__ __launch_bounds__(128) void gat_sum4_k(
    const float4* __restrict__ xl, const float* __restrict__ w,
    const int* __restrict__ rowptr, const int* __restrict__ colv,
    float4* __restrict__ accm, int C4, int Nn, int Etot)
{
    int dst = blockIdx.x;
    int h = blockIdx.y;
    int tid = threadIdx.x;
    const float4* xlh = xl + (size_t)h * Nn * C4;
    const float* wh = w + (size_t)h * Etot;
    const float4 z4 = make_float4(0.f, 0.f, 0.f, 0.f);

    float4 acc[NV];
#pragma unroll
    for (int j = 0; j < NV; j++) acc[j] = z4;
    float l = 0.f;

    int e0 = rowptr[dst], e1 = rowptr[dst + 1];
    int e = e0;
    for (; e + 1 < e1; e += 2) {
        int s0 = __ldg(&colv[e]);
        int s1 = __ldg(&colv[e + 1]);
        float w0 = __ldg(&wh[e]);
        float w1 = __ldg(&wh[e + 1]);
        l += w0 + w1;
        const float4* p0 = xlh + (size_t)s0 * C4;
        const float4* p1 = xlh + (size_t)s1 * C4;
#pragma unroll
        for (int j = 0; j < NV; j++) {
            int idx = tid + j * 128;
            if (EXACT || idx < C4) {
                float4 x0 = __ldg(&p0[idx]);
                float4 x1 = __ldg(&p1[idx]);
                acc[j].x += w0 * x0.x + w1 * x1.x;
                acc[j].y += w0 * x0.y + w1 * x1.y;
                acc[j].z += w0 * x0.z + w1 * x1.z;
                acc[j].w += w0 * x0.w + w1 * x1.w;
            }
        }
    }
    if (e < e1) {
        int s0 = __ldg(&colv[e]);
        float w0 = __ldg(&wh[e]);
        l += w0;
        const float4* p0 = xlh + (size_t)s0 * C4;
#pragma unroll
        for (int j = 0; j < NV; j++) {
            int idx = tid + j * 128;
            if (EXACT || idx < C4) {
                float4 x0 = __ldg(&p0[idx]);
                acc[j].x += w0 * x0.x;
                acc[j].y += w0 * x0.y;
                acc[j].z += w0 * x0.z;
                acc[j].w += w0 * x0.w;
            }
        }
    }

    float inv = 1.f / l;
    float4* dp = accm + ((size_t)h * Nn + dst) * C4;
#pragma unroll
    for (int j = 0; j < NV; j++) {
        int idx = tid + j * 128;
        if (EXACT || idx < C4) {
            float4 v = acc[j];
            v.x *= inv; v.y *= inv; v.z *= inv; v.w *= inv;
            dp[idx] = v;
        }
    }
}

// ---------------------------------------------------------------------------
// Head mean + bias + optional leaky; writes float (final) or half (next layer)
// ---------------------------------------------------------------------------
template <typename T>
__global__ void mean_bias_act_k(const float* __restrict__ accm,
                                const float* __restrict__ bias,
                                T* __restrict__ out,
                                int total, int C, size_t sliceN, int H,
                                float invH, float slope, int do_act) {
    int i = blockIdx.x * blockDim.x + threadIdx.x;
    if (i >= total) return;
    float s = 0.f;
    for (int h = 0; h < H; h++) s += accm[(size_t)h * sliceN + i];
    float v = s * invH + bias[i % C];
    if (do_act) v = v > 0.f ? v : slope * v;
    out[i] = (T)v;
}

// ---------------------------------------------------------------------------
// host orchestration
// ---------------------------------------------------------------------------
static void run_gemm(const __half* A, const __half* Bt, const float* bias,
                     float* C, int M, int K, int lda, int ldb, int Ncols, int Cdim) {
    dim3 grid((M + 127) / 128, Ncols / 128);
    gemm_h_k<<<grid, 128, GEMM_SMEM>>>(A, Bt, bias, C, M, K, lda, ldb, Ncols, Cdim);
}

template <typename TOUT>
static void run_layer(const __half* hin, int fi, int lda, int fo,
                      const float* Wl, const float* bl,
                      const float* Wr, const float* br,
                      const float* att, const float* bias,
                      float* xl, float* xr, float* accm, float* wbuf,
                      __half* wlh, __half* wrh,
                      const int* rowptr, const int* colv, const int* dstv,
                      TOUT* hout, int N, int H, int Etot, bool act) {
    int Ncols = H * fo;
    int ldwt = (fi + 7) & ~7;
    {
        dim3 tb(32, 8);
        dim3 tg((Ncols + 31) / 32, (ldwt + 31) / 32);
        conv_trans_k<<<tg, tb>>>(Wl, wlh, fi, Ncols, ldwt);
        conv_trans_k<<<tg, tb>>>(Wr, wrh, fi, Ncols, ldwt);
    }
    run_gemm(hin, wlh, bl, xl, N, fi, lda, ldwt, Ncols, fo);
    run_gemm(hin, wrh, br, xr, N, fi, lda, ldwt, Ncols, fo);

    int C4 = fo / 4;
    dim3 lg((Etot + 63) / 64, H);
    dim3 sg(N, H);
    if (fo == 128) {
        gat_logit_k<1, true><<<lg, 256>>>(
            (const float4*)xl, (const float4*)xr, (const float4*)att,
            colv, dstv, wbuf, C4, N, Etot);
        gat_sum_k<<<sg, 128>>>(xl, wbuf, rowptr, colv, accm, fo, N, Etot);
    } else if (fo == 512) {
        gat_logit_k<4, true><<<lg, 256>>>(
            (const float4*)xl, (const float4*)xr, (const float4*)att,
            colv, dstv, wbuf, C4, N, Etot);
        gat_sum4_k<1, true><<<sg, 128>>>(
            (const float4*)xl, wbuf, rowptr, colv, (float4*)accm, C4, N, Etot);
    } else {  // 1028 -> C4 = 257
        gat_logit_k<9, false><<<lg, 256>>>(
            (const float4*)xl, (const float4*)xr, (const float4*)att,
            colv, dstv, wbuf, C4, N, Etot);
        gat_sum4_k<3, false><<<sg, 128>>>(
            (const float4*)xl, wbuf, rowptr, colv, (float4*)accm, C4, N, Etot);
    }

    int total = N * fo;
    mean_bias_act_k<TOUT><<<(total + 255) / 256, 256>>>(
        accm, bias, hout, total, fo, (size_t)N * fo, H,
        1.f / (float)H, 0.01f, act ? 1 : 0);
}

extern "C" void kernel_launch(void* const* d_in, const int* in_sizes, int n_in,
                              void* d_out, int out_size) {
    const float* x  = (const float*)d_in[0];
    const int*   ei = (const int*)d_in[1];

    const float* W1l = (const float*)d_in[2];
    const float* b1l = (const float*)d_in[3];
    const float* W1r = (const float*)d_in[4];
    const float* b1r = (const float*)d_in[5];
    const float* at1 = (const float*)d_in[6];
    const float* bi1 = (const float*)d_in[7];
    const float* W2l = (const float*)d_in[8];
    const float* b2l = (const float*)d_in[9];
    const float* W2r = (const float*)d_in[10];
    const float* b2r = (const float*)d_in[11];
    const float* at2 = (const float*)d_in[12];
    const float* bi2 = (const float*)d_in[13];
    const float* W3l = (const float*)d_in[14];
    const float* b3l = (const float*)d_in[15];
    const float* W3r = (const float*)d_in[16];
    const float* b3r = (const float*)d_in[17];
    const float* at3 = (const float*)d_in[18];
    const float* bi3 = (const float*)d_in[19];

    int N = in_sizes[0] / 4;
    int E = in_sizes[1] / 2;
    int f1 = in_sizes[7];
    int f2 = in_sizes[13];
    int f3 = in_sizes[19];
    int H  = in_sizes[3] / f1;
    int Etot = E + N;

    cudaFuncSetAttribute(gemm_h_k, cudaFuncAttributeMaxDynamicSharedMemorySize,
                         GEMM_SMEM);

    float *xl, *xr, *accm, *wbuf;
    __half *wlh, *wrh, *a0h, *h1h, *h2h;
    int *deg, *rowptr, *cursor, *colv, *dstv;
    cudaGetSymbolAddress((void**)&xl, g_xl);
    cudaGetSymbolAddress((void**)&xr, g_xr);
    cudaGetSymbolAddress((void**)&accm, g_acc);
    cudaGetSymbolAddress((void**)&wbuf, g_w);
    cudaGetSymbolAddress((void**)&wlh, g_wlh);
    cudaGetSymbolAddress((void**)&wrh, g_wrh);
    cudaGetSymbolAddress((void**)&a0h, g_a0h);
    cudaGetSymbolAddress((void**)&h1h, g_h1h);
    cudaGetSymbolAddress((void**)&h2h, g_h2h);
    cudaGetSymbolAddress((void**)&deg, g_deg);
    cudaGetSymbolAddress((void**)&rowptr, g_rowptr);
    cudaGetSymbolAddress((void**)&cursor, g_cursor);
    cudaGetSymbolAddress((void**)&colv, g_col);
    cudaGetSymbolAddress((void**)&dstv, g_dst);

    // --- CSR build (by destination) ---
    init_deg_k<<<(N + 255) / 256, 256>>>(deg, N);
    count_deg_k<<<(E + 255) / 256, 256>>>(ei, deg, E);
    scan_rowptr_k<<<1, 1024>>>(deg, rowptr, N);
    copy_cursor_k<<<(N + 255) / 256, 256>>>(rowptr, cursor, N);
    scatter_edges_k<<<(E + 255) / 256, 256>>>(ei, cursor, colv, dstv, E);
    scatter_loops_k<<<(N + 255) / 256, 256>>>(cursor, colv, dstv, N);

    // --- x -> half (padded to 8 columns) ---
    conv_x_k<<<(N * 8 + 255) / 256, 256>>>(x, a0h, N, 4, 8);

    // --- 3 GATv2 layers ---
    run_layer<__half>(a0h, 4, 8, f1, W1l, b1l, W1r, b1r, at1, bi1,
                      xl, xr, accm, wbuf, wlh, wrh, rowptr, colv, dstv,
                      h1h, N, H, Etot, true);
    run_layer<__half>(h1h, f1, f1, f2, W2l, b2l, W2r, b2r, at2, bi2,
                      xl, xr, accm, wbuf, wlh, wrh, rowptr, colv, dstv,
                      h2h, N, H, Etot, true);
    run_layer<float>(h2h, f2, f2, f3, W3l, b3l, W3r, b3r, at3, bi3,
                     xl, xr, accm, wbuf, wlh, wrh, rowptr, colv, dstv,
                     (float*)d_out, N, H, Etot, false);
}

// round 13
// speedup vs baseline: 1.1110x; 1.1005x over previous
#include <cuda_runtime.h>
#include <cuda_fp16.h>
#include <cstdint>
#include <cstddef>

// ---------------------------------------------------------------------------
// GATv2 x3 layers.  Dims: 4 -> 128 -> 512 -> 1028, H=32 heads, head-mean.
//   GEMMs: mma.sync.m16n8k16 fp16 (fp32 accum), 128x128 CTA tile, cp.async
//     double buffer, ldmatrix (LDSM.x4) fragment loads, fp32 head-major
//     outputs xl/xr: [h][n][c].
//   Edge phase: fused online-softmax, float4 gathers, 2 edges per barrier
//     (best variant from R9).
// ---------------------------------------------------------------------------

#define MAX_N 10000
#define MAX_E 160000
#define MAX_EL (MAX_E + MAX_N)

// scratch (allocation-free rule: __device__ globals)
__device__ float  g_xl[328960000];          // 10000 * 32 * 1028 (head-major)
__device__ float  g_xr[328960000];
__device__ float  g_acc[328960000];
__device__ __half g_wlh[16842752];          // transposed half weights
__device__ __half g_wrh[16842752];
__device__ __half g_a0h[80000];             // x as half, padded K=8
__device__ __half g_h1h[1280000];           // N x 128
__device__ __half g_h2h[5120000];           // N x 512
__device__ int    g_deg[MAX_N];
__device__ int    g_rowptr[MAX_N + 1];
__device__ int    g_cursor[MAX_N];
__device__ int    g_col[MAX_EL];

// ---------------------------------------------------------------------------
// helpers
// ---------------------------------------------------------------------------
__device__ __forceinline__ void cp16(uint32_t dst, const void* src, int bytes) {
    asm volatile("cp.async.cg.shared.global [%0], [%1], 16, %2;"
                 :: "r"(dst), "l"(src), "r"(bytes) : "memory");
}
__device__ __forceinline__ void cp_commit() {
    asm volatile("cp.async.commit_group;" ::: "memory");
}
template <int N>
__device__ __forceinline__ void cp_wait() {
    asm volatile("cp.async.wait_group %0;" :: "n"(N) : "memory");
}
__device__ __forceinline__ uint32_t smem_u32(const void* p) {
    uint32_t a;
    asm("{ .reg .u64 t; cvta.to.shared.u64 t, %1; cvt.u32.u64 %0, t; }"
        : "=r"(a) : "l"(p));
    return a;
}
__device__ __forceinline__ void ldsm_x4(uint32_t& r0, uint32_t& r1,
                                        uint32_t& r2, uint32_t& r3, uint32_t addr) {
    asm volatile("ldmatrix.sync.aligned.m8n8.x4.shared.b16 {%0,%1,%2,%3}, [%4];"
                 : "=r"(r0), "=r"(r1), "=r"(r2), "=r"(r3) : "r"(addr));
}
__device__ __forceinline__ void mma_fp16(float& c0, float& c1, float& c2, float& c3,
                                         uint32_t a0, uint32_t a1, uint32_t a2, uint32_t a3,
                                         uint32_t b0, uint32_t b1) {
    asm volatile(
        "mma.sync.aligned.m16n8k16.row.col.f32.f16.f16.f32 "
        "{%0,%1,%2,%3}, {%4,%5,%6,%7}, {%8,%9}, {%0,%1,%2,%3};"
        : "+f"(c0), "+f"(c1), "+f"(c2), "+f"(c3)
        : "r"(a0), "r"(a1), "r"(a2), "r"(a3), "r"(b0), "r"(b1));
}
__device__ __forceinline__ float lrelu02(float v) {
    return v > 0.f ? v : 0.2f * v;
}

// ---------------------------------------------------------------------------
// weight convert + transpose:  Wt[n][k] = (half)W[k][n]
// ---------------------------------------------------------------------------
__global__ void conv_trans_k(const float* __restrict__ W, __half* __restrict__ Wt,
                             int K, int Ncols, int ldwt) {
    __shared__ float t[32][33];
    int n0 = blockIdx.x * 32;
    int k0 = blockIdx.y * 32;
    int tx = threadIdx.x;
    int ty = threadIdx.y;
    for (int i = ty; i < 32; i += 8) {
        int k = k0 + i;
        int n = n0 + tx;
        t[i][tx] = (k < K && n < Ncols) ? W[(size_t)k * Ncols + n] : 0.f;
    }
    __syncthreads();
    for (int i = ty; i < 32; i += 8) {
        int n = n0 + i;
        int k = k0 + tx;
        if (n < Ncols && k < ldwt)
            Wt[(size_t)n * ldwt + k] = __float2half(t[tx][i]);
    }
}

__global__ void conv_x_k(const float* __restrict__ x, __half* __restrict__ out,
                         int N, int K, int lda) {
    int i = blockIdx.x * blockDim.x + threadIdx.x;
    if (i < N * lda) {
        int row = i / lda, col = i - row * lda;
        out[i] = __float2half(col < K ? x[row * K + col] : 0.f);
    }
}

// ---------------------------------------------------------------------------
// fp16 GEMM:  C_out[h][m][c] = (A @ Bt^T)[m, h*C+c] + bias   (head-major fp32)
// ldmatrix fragment loads; conflict-free for AS=40 (80B row stride).
// ---------------------------------------------------------------------------
#define AS 40
#define TILE_BYTES (128 * AS * 2)           // 10240
#define GEMM_SMEM (4 * TILE_BYTES)          // 40960

__global__ __launch_bounds__(128, 2) void gemm_h_k(
    const __half* __restrict__ A, const __half* __restrict__ Bt,
    const float* __restrict__ bias, float* __restrict__ Cmat,
    int M, int K, int lda, int ldb, int Ncols, int Cdim)
{
    extern __shared__ __align__(16) __half dyn[];
    __half* sA[2] = { dyn,              dyn + TILE_BYTES / 2 };
    __half* sB[2] = { dyn + TILE_BYTES, dyn + 3 * TILE_BYTES / 2 };

    const int tid = threadIdx.x;
    const int wid = tid >> 5;
    const int lane = tid & 31;
    const int gid = lane >> 2;
    const int tig = lane & 3;
    const int m0 = blockIdx.x * 128;
    const int n0 = blockIdx.y * 128;
    const int warpM = (wid >> 1) * 64;
    const int warpN = (wid & 1) * 64;

    // ldmatrix per-lane byte offsets (within a tile buffer)
    // A: rows = m (lane&15), k offset = (lane>>4)*8
    const uint32_t aOff2 = 2u * ((lane & 15) * AS + ((lane >> 4) << 3));
    // B: rows = n = ((lane>>4)<<3) + (lane&7), k offset = ((lane>>3)&1)*8
    const uint32_t bOff2 = 2u * ((((lane >> 4) << 3) + (lane & 7)) * AS
                                 + (((lane >> 3) & 1) << 3));

    const int nChunks = (K + 31) / 32;

    auto stage = [&](int chunk, int b) {
        const int k0 = chunk * 32;
        uint32_t sAu = smem_u32(sA[b]);
        uint32_t sBu = smem_u32(sB[b]);
#pragma unroll
        for (int it = 0; it < 4; it++) {
            int idx = tid + it * 128;
            int row = idx >> 2;
            int seg = (idx & 3) * 8;
            int gk = k0 + seg;
            int rem = (K - gk) * 2;
            int bytes = (m0 + row < M) ? (rem < 0 ? 0 : (rem > 16 ? 16 : rem)) : 0;
            const __half* src = bytes ? &A[(size_t)(m0 + row) * lda + gk] : A;
            cp16(sAu + (row * AS + seg) * 2, src, bytes);
        }
#pragma unroll
        for (int it = 0; it < 4; it++) {
            int idx = tid + it * 128;
            int row = idx >> 2;
            int seg = (idx & 3) * 8;
            int gk = k0 + seg;
            int rem = (K - gk) * 2;
            int bytes = rem < 0 ? 0 : (rem > 16 ? 16 : rem);
            const __half* src = bytes ? &Bt[(size_t)(n0 + row) * ldb + gk] : Bt;
            cp16(sBu + (row * AS + seg) * 2, src, bytes);
        }
        cp_commit();
    };

    float acc[4][8][4];
#pragma unroll
    for (int i = 0; i < 4; i++)
#pragma unroll
        for (int j = 0; j < 8; j++)
#pragma unroll
            for (int q = 0; q < 4; q++) acc[i][j][q] = 0.f;

    stage(0, 0);

    for (int t = 0; t < nChunks; t++) {
        if (t + 1 < nChunks) { stage(t + 1, (t + 1) & 1); cp_wait<1>(); }
        else                 { cp_wait<0>(); }
        __syncthreads();

        uint32_t aBase = smem_u32(sA[t & 1]);
        uint32_t bBase = smem_u32(sB[t & 1]);
#pragma unroll
        for (int kk = 0; kk < 32; kk += 16) {
            uint32_t af[4][4];
#pragma unroll
            for (int i = 0; i < 4; i++) {
                uint32_t addr = aBase + 2u * ((warpM + i * 16) * AS + kk) + aOff2;
                ldsm_x4(af[i][0], af[i][1], af[i][2], af[i][3], addr);
            }
            uint32_t bf[8][2];
#pragma unroll
            for (int j2 = 0; j2 < 4; j2++) {
                uint32_t addr = bBase + 2u * ((warpN + j2 * 16) * AS + kk) + bOff2;
                ldsm_x4(bf[2 * j2][0], bf[2 * j2][1],
                        bf[2 * j2 + 1][0], bf[2 * j2 + 1][1], addr);
            }
#pragma unroll
            for (int i = 0; i < 4; i++)
#pragma unroll
                for (int j = 0; j < 8; j++)
                    mma_fp16(acc[i][j][0], acc[i][j][1], acc[i][j][2], acc[i][j][3],
                             af[i][0], af[i][1], af[i][2], af[i][3],
                             bf[j][0], bf[j][1]);
        }
        __syncthreads();
    }

    int hj[8], cj[8];
    float bj0[8], bj1[8];
#pragma unroll
    for (int j = 0; j < 8; j++) {
        int col = n0 + warpN + j * 8 + tig * 2;
        int h = col / Cdim;
        hj[j] = h;
        cj[j] = col - h * Cdim;
        bj0[j] = __ldg(&bias[col]);
        bj1[j] = __ldg(&bias[col + 1]);
    }
#pragma unroll
    for (int i = 0; i < 4; i++) {
        int r0 = m0 + warpM + i * 16 + gid;
#pragma unroll
        for (int j = 0; j < 8; j++) {
            float* base = &Cmat[((size_t)hj[j] * M) * Cdim + cj[j]];
            if (r0 < M) {
                float2 v = make_float2(acc[i][j][0] + bj0[j], acc[i][j][1] + bj1[j]);
                *reinterpret_cast<float2*>(&base[(size_t)r0 * Cdim]) = v;
            }
            if (r0 + 8 < M) {
                float2 v = make_float2(acc[i][j][2] + bj0[j], acc[i][j][3] + bj1[j]);
                *reinterpret_cast<float2*>(&base[(size_t)(r0 + 8) * Cdim]) = v;
            }
        }
    }
}

// ---------------------------------------------------------------------------
// CSR construction
// ---------------------------------------------------------------------------
__global__ void init_deg_k(int* deg, int n) {
    int i = blockIdx.x * blockDim.x + threadIdx.x;
    if (i < n) deg[i] = 1;
}
__global__ void count_deg_k(const int* __restrict__ ei, int* deg, int E) {
    int e = blockIdx.x * blockDim.x + threadIdx.x;
    if (e < E) atomicAdd(&deg[ei[E + e]], 1);
}
__global__ void scan_rowptr_k(const int* __restrict__ deg, int* rowptr, int n) {
    __shared__ int sm[1024];
    __shared__ int carry;
    int tid = threadIdx.x;
    if (tid == 0) { carry = 0; rowptr[0] = 0; }
    __syncthreads();
    for (int base = 0; base < n; base += 1024) {
        int i = base + tid;
        int v = (i < n) ? deg[i] : 0;
        sm[tid] = v;
        __syncthreads();
        for (int off = 1; off < 1024; off <<= 1) {
            int t = (tid >= off) ? sm[tid - off] : 0;
            __syncthreads();
            sm[tid] += t;
            __syncthreads();
        }
        if (i < n) rowptr[i + 1] = carry + sm[tid];
        __syncthreads();
        if (tid == 0) carry += sm[1023];
        __syncthreads();
    }
}
__global__ void copy_cursor_k(const int* __restrict__ rowptr, int* cursor, int n) {
    int i = blockIdx.x * blockDim.x + threadIdx.x;
    if (i < n) cursor[i] = rowptr[i];
}
__global__ void scatter_edges_k(const int* __restrict__ ei, int* cursor,
                                int* colv, int E) {
    int e = blockIdx.x * blockDim.x + threadIdx.x;
    if (e < E) {
        int s = ei[e];
        int d = ei[E + e];
        int pos = atomicAdd(&cursor[d], 1);
        colv[pos] = s;
    }
}
__global__ void scatter_loops_k(int* cursor, int* colv, int n) {
    int i = blockIdx.x * blockDim.x + threadIdx.x;
    if (i < n) {
        int pos = atomicAdd(&cursor[i], 1);
        colv[pos] = i;
    }
}

// ---------------------------------------------------------------------------
// Edge attention, scalar path (C == 128).  Block = (dst, head), 128 threads.
// ---------------------------------------------------------------------------
__global__ __launch_bounds__(128) void gat_edge_k(
    const float* __restrict__ xl, const float* __restrict__ xr,
    const float* __restrict__ att, const int* __restrict__ rowptr,
    const int* __restrict__ colv, float* __restrict__ accm,
    int C, int Nn)
{
    int dst = blockIdx.x;
    int h = blockIdx.y;
    int tid = threadIdx.x;
    __shared__ float ws[2][4];

    const float* xlh = xl + (size_t)h * Nn * C;
    const float* xrh = xr + (size_t)h * Nn * C;

    float a = att[h * C + tid];
    float xd = xrh[(size_t)dst * C + tid];
    float acc = 0.f;

    float m = -3.4e38f, l = 0.f;
    int e0 = rowptr[dst], e1 = rowptr[dst + 1];
    for (int e = e0; e < e1; e++) {
        int s = __ldg(&colv[e]);
        float xv = __ldg(&xlh[(size_t)s * C + tid]);
        float p = a * lrelu02(xv + xd);
#pragma unroll
        for (int o = 16; o > 0; o >>= 1) p += __shfl_xor_sync(0xffffffffu, p, o);
        int slot = e & 1;
        if ((tid & 31) == 0) ws[slot][tid >> 5] = p;
        __syncthreads();
        float ev = ws[slot][0] + ws[slot][1] + ws[slot][2] + ws[slot][3];

        float mn = fmaxf(m, ev);
        float sc = __expf(m - mn);
        float w  = __expf(ev - mn);
        acc = acc * sc + w * xv;
        l = l * sc + w;
        m = mn;
    }
    accm[((size_t)h * Nn + dst) * C + tid] = acc / l;
}

// ---------------------------------------------------------------------------
// Edge attention, float4 path (C % 4 == 0).  Block = (dst, head), 128 thr.
// Processes 2 edges per barrier.  NV = ceil(C/4 / 128).
// ---------------------------------------------------------------------------
template <int NV, bool EXACT>
__global__ __launch_bounds__(128) void gat_edge4_k(
    const float4* __restrict__ xl, const float4* __restrict__ xr,
    const float4* __restrict__ att, const int* __restrict__ rowptr,
    const int* __restrict__ colv, float4* __restrict__ accm,
    int C4, int Nn)
{
    int dst = blockIdx.x;
    int h = blockIdx.y;
    int tid = threadIdx.x;
    __shared__ float ws[2][2][4];

    const float4* xlh = xl + (size_t)h * Nn * C4;
    const float4* xrh = xr + (size_t)h * Nn * C4;
    const float4 z4 = make_float4(0.f, 0.f, 0.f, 0.f);

    float4 a[NV], xd[NV], acc[NV];
#pragma unroll
    for (int j = 0; j < NV; j++) {
        int idx = tid + j * 128;
        bool ok = EXACT || (idx < C4);
        a[j]   = ok ? __ldg(&att[(size_t)h * C4 + idx]) : z4;
        xd[j]  = ok ? __ldg(&xrh[(size_t)dst * C4 + idx]) : z4;
        acc[j] = z4;
    }

    float m = -3.4e38f, l = 0.f;
    int e0 = rowptr[dst], e1 = rowptr[dst + 1];
    int deg = e1 - e0;
    int npair = deg >> 1;

    for (int it = 0; it < npair; it++) {
        int e = e0 + it * 2;
        int s0 = __ldg(&colv[e]);
        int s1 = __ldg(&colv[e + 1]);
        const float4* v0 = xlh + (size_t)s0 * C4;
        const float4* v1 = xlh + (size_t)s1 * C4;
        float4 xs0[NV], xs1[NV];
        float p0 = 0.f, p1 = 0.f;
#pragma unroll
        for (int j = 0; j < NV; j++) {
            int idx = tid + j * 128;
            bool ok = EXACT || (idx < C4);
            float4 x0 = ok ? __ldg(&v0[idx]) : z4;
            float4 x1 = ok ? __ldg(&v1[idx]) : z4;
            xs0[j] = x0; xs1[j] = x1;
            p0 = fmaf(a[j].x, lrelu02(x0.x + xd[j].x), p0);
            p0 = fmaf(a[j].y, lrelu02(x0.y + xd[j].y), p0);
            p0 = fmaf(a[j].z, lrelu02(x0.z + xd[j].z), p0);
            p0 = fmaf(a[j].w, lrelu02(x0.w + xd[j].w), p0);
            p1 = fmaf(a[j].x, lrelu02(x1.x + xd[j].x), p1);
            p1 = fmaf(a[j].y, lrelu02(x1.y + xd[j].y), p1);
            p1 = fmaf(a[j].z, lrelu02(x1.z + xd[j].z), p1);
            p1 = fmaf(a[j].w, lrelu02(x1.w + xd[j].w), p1);
        }
#pragma unroll
        for (int o = 16; o > 0; o >>= 1) {
            p0 += __shfl_xor_sync(0xffffffffu, p0, o);
            p1 += __shfl_xor_sync(0xffffffffu, p1, o);
        }
        int sl = it & 1;
        if ((tid & 31) == 0) {
            ws[sl][0][tid >> 5] = p0;
            ws[sl][1][tid >> 5] = p1;
        }
        __syncthreads();
        float ev0 = ws[sl][0][0] + ws[sl][0][1] + ws[sl][0][2] + ws[sl][0][3];
        float ev1 = ws[sl][1][0] + ws[sl][1][1] + ws[sl][1][2] + ws[sl][1][3];

        float mn = fmaxf(m, fmaxf(ev0, ev1));
        float sc = __expf(m - mn);
        float w0 = __expf(ev0 - mn);
        float w1 = __expf(ev1 - mn);
#pragma unroll
        for (int j = 0; j < NV; j++) {
            acc[j].x = acc[j].x * sc + w0 * xs0[j].x + w1 * xs1[j].x;
            acc[j].y = acc[j].y * sc + w0 * xs0[j].y + w1 * xs1[j].y;
            acc[j].z = acc[j].z * sc + w0 * xs0[j].z + w1 * xs1[j].z;
            acc[j].w = acc[j].w * sc + w0 * xs0[j].w + w1 * xs1[j].w;
        }
        l = l * sc + w0 + w1;
        m = mn;
    }

    if (deg & 1) {
        int e = e1 - 1;
        int s0 = __ldg(&colv[e]);
        const float4* v0 = xlh + (size_t)s0 * C4;
        float4 xs0[NV];
        float p0 = 0.f;
#pragma unroll
        for (int j = 0; j < NV; j++) {
            int idx = tid + j * 128;
            bool ok = EXACT || (idx < C4);
            float4 x0 = ok ? __ldg(&v0[idx]) : z4;
            xs0[j] = x0;
            p0 = fmaf(a[j].x, lrelu02(x0.x + xd[j].x), p0);
            p0 = fmaf(a[j].y, lrelu02(x0.y + xd[j].y), p0);
            p0 = fmaf(a[j].z, lrelu02(x0.z + xd[j].z), p0);
            p0 = fmaf(a[j].w, lrelu02(x0.w + xd[j].w), p0);
        }
#pragma unroll
        for (int o = 16; o > 0; o >>= 1) p0 += __shfl_xor_sync(0xffffffffu, p0, o);
        int sl = npair & 1;
        if ((tid & 31) == 0) ws[sl][0][tid >> 5] = p0;
        __syncthreads();
        float pv0 = ws[sl][0][0] + ws[sl][0][1] + ws[sl][0][2] + ws[sl][0][3];

        float mn = fmaxf(m, pv0);
        float sc = __expf(m - mn);
        float w0 = __expf(pv0 - mn);
#pragma unroll
        for (int j = 0; j < NV; j++) {
            acc[j].x = acc[j].x * sc + w0 * xs0[j].x;
            acc[j].y = acc[j].y * sc + w0 * xs0[j].y;
            acc[j].z = acc[j].z * sc + w0 * xs0[j].z;
            acc[j].w = acc[j].w * sc + w0 * xs0[j].w;
        }
        l = l * sc + w0;
    }

    float inv = 1.f / l;
    float4* dp = accm + ((size_t)h * Nn + dst) * C4;
#pragma unroll
    for (int j = 0; j < NV; j++) {
        int idx = tid + j * 128;
        if (EXACT || idx < C4) {
            float4 v = acc[j];
            v.x *= inv; v.y *= inv; v.z *= inv; v.w *= inv;
            dp[idx] = v;
        }
    }
}

// ---------------------------------------------------------------------------
// Head mean + bias + optional leaky; writes float (final) or half (next layer)
// ---------------------------------------------------------------------------
template <typename T>
__global__ void mean_bias_act_k(const float* __restrict__ accm,
                                const float* __restrict__ bias,
                                T* __restrict__ out,
                                int total, int C, size_t sliceN, int H,
                                float invH, float slope, int do_act) {
    int i = blockIdx.x * blockDim.x + threadIdx.x;
    if (i >= total) return;
    float s = 0.f;
    for (int h = 0; h < H; h++) s += accm[(size_t)h * sliceN + i];
    float v = s * invH + bias[i % C];
    if (do_act) v = v > 0.f ? v : slope * v;
    out[i] = (T)v;
}

// ---------------------------------------------------------------------------
// host orchestration
// ---------------------------------------------------------------------------
static void run_gemm(const __half* A, const __half* Bt, const float* bias,
                     float* C, int M, int K, int lda, int ldb, int Ncols, int Cdim) {
    dim3 grid((M + 127) / 128, Ncols / 128);
    gemm_h_k<<<grid, 128, GEMM_SMEM>>>(A, Bt, bias, C, M, K, lda, ldb, Ncols, Cdim);
}

template <typename TOUT>
static void run_layer(const __half* hin, int fi, int lda, int fo,
                      const float* Wl, const float* bl,
                      const float* Wr, const float* br,
                      const float* att, const float* bias,
                      float* xl, float* xr, float* accm,
                      __half* wlh, __half* wrh,
                      const int* rowptr, const int* colv,
                      TOUT* hout, int N, int H, bool act) {
    int Ncols = H * fo;
    int ldwt = (fi + 7) & ~7;
    {
        dim3 tb(32, 8);
        dim3 tg((Ncols + 31) / 32, (ldwt + 31) / 32);
        conv_trans_k<<<tg, tb>>>(Wl, wlh, fi, Ncols, ldwt);
        conv_trans_k<<<tg, tb>>>(Wr, wrh, fi, Ncols, ldwt);
    }
    run_gemm(hin, wlh, bl, xl, N, fi, lda, ldwt, Ncols, fo);
    run_gemm(hin, wrh, br, xr, N, fi, lda, ldwt, Ncols, fo);

    dim3 eg(N, H);
    int C4 = fo / 4;
    if (fo == 128) {
        gat_edge_k<<<eg, 128>>>(xl, xr, att, rowptr, colv, accm, fo, N);
    } else if (fo == 512) {
        gat_edge4_k<1, true><<<eg, 128>>>(
            (const float4*)xl, (const float4*)xr, (const float4*)att,
            rowptr, colv, (float4*)accm, C4, N);
    } else {  // 1028 -> C4 = 257
        gat_edge4_k<3, false><<<eg, 128>>>(
            (const float4*)xl, (const float4*)xr, (const float4*)att,
            rowptr, colv, (float4*)accm, C4, N);
    }

    int total = N * fo;
    mean_bias_act_k<TOUT><<<(total + 255) / 256, 256>>>(
        accm, bias, hout, total, fo, (size_t)N * fo, H,
        1.f / (float)H, 0.01f, act ? 1 : 0);
}

extern "C" void kernel_launch(void* const* d_in, const int* in_sizes, int n_in,
                              void* d_out, int out_size) {
    const float* x  = (const float*)d_in[0];
    const int*   ei = (const int*)d_in[1];

    const float* W1l = (const float*)d_in[2];
    const float* b1l = (const float*)d_in[3];
    const float* W1r = (const float*)d_in[4];
    const float* b1r = (const float*)d_in[5];
    const float* at1 = (const float*)d_in[6];
    const float* bi1 = (const float*)d_in[7];
    const float* W2l = (const float*)d_in[8];
    const float* b2l = (const float*)d_in[9];
    const float* W2r = (const float*)d_in[10];
    const float* b2r = (const float*)d_in[11];
    const float* at2 = (const float*)d_in[12];
    const float* bi2 = (const float*)d_in[13];
    const float* W3l = (const float*)d_in[14];
    const float* b3l = (const float*)d_in[15];
    const float* W3r = (const float*)d_in[16];
    const float* b3r = (const float*)d_in[17];
    const float* at3 = (const float*)d_in[18];
    const float* bi3 = (const float*)d_in[19];

    int N = in_sizes[0] / 4;
    int E = in_sizes[1] / 2;
    int f1 = in_sizes[7];
    int f2 = in_sizes[13];
    int f3 = in_sizes[19];
    int H  = in_sizes[3] / f1;

    cudaFuncSetAttribute(gemm_h_k, cudaFuncAttributeMaxDynamicSharedMemorySize,
                         GEMM_SMEM);

    float *xl, *xr, *accm;
    __half *wlh, *wrh, *a0h, *h1h, *h2h;
    int *deg, *rowptr, *cursor, *colv;
    cudaGetSymbolAddress((void**)&xl, g_xl);
    cudaGetSymbolAddress((void**)&xr, g_xr);
    cudaGetSymbolAddress((void**)&accm, g_acc);
    cudaGetSymbolAddress((void**)&wlh, g_wlh);
    cudaGetSymbolAddress((void**)&wrh, g_wrh);
    cudaGetSymbolAddress((void**)&a0h, g_a0h);
    cudaGetSymbolAddress((void**)&h1h, g_h1h);
    cudaGetSymbolAddress((void**)&h2h, g_h2h);
    cudaGetSymbolAddress((void**)&deg, g_deg);
    cudaGetSymbolAddress((void**)&rowptr, g_rowptr);
    cudaGetSymbolAddress((void**)&cursor, g_cursor);
    cudaGetSymbolAddress((void**)&colv, g_col);

    // --- CSR build (by destination) ---
    init_deg_k<<<(N + 255) / 256, 256>>>(deg, N);
    count_deg_k<<<(E + 255) / 256, 256>>>(ei, deg, E);
    scan_rowptr_k<<<1, 1024>>>(deg, rowptr, N);
    copy_cursor_k<<<(N + 255) / 256, 256>>>(rowptr, cursor, N);
    scatter_edges_k<<<(E + 255) / 256, 256>>>(ei, cursor, colv, E);
    scatter_loops_k<<<(N + 255) / 256, 256>>>(cursor, colv, N);

    // --- x -> half (padded to 8 columns) ---
    conv_x_k<<<(N * 8 + 255) / 256, 256>>>(x, a0h, N, 4, 8);

    // --- 3 GATv2 layers ---
    run_layer<__half>(a0h, 4, 8, f1, W1l, b1l, W1r, b1r, at1, bi1,
                      xl, xr, accm, wlh, wrh, rowptr, colv, h1h, N, H, true);
    run_layer<__half>(h1h, f1, f1, f2, W2l, b2l, W2r, b2r, at2, bi2,
                      xl, xr, accm, wlh, wrh, rowptr, colv, h2h, N, H, true);
    run_layer<float>(h2h, f2, f2, f3, W3l, b3l, W3r, b3r, at3, bi3,
                     xl, xr, accm, wlh, wrh, rowptr, colv, (float*)d_out, N, H, false);
}